// round 1
// baseline (speedup 1.0000x reference)
#include <cuda_runtime.h>

#define N_FEAT 1024
#define N_LAYER 4
#define THREADS 256
#define WPB (THREADS / 32)

// h[j][i] = <b_j, w_i>; bsum = b0+b1+b2+b3
__device__ float g_h[N_LAYER][N_LAYER];
__device__ float g_bsum[N_FEAT];

__global__ __launch_bounds__(1024) void precompute_kernel(
    const float* __restrict__ w, const float* __restrict__ b)
{
    int tid = threadIdx.x;  // 1024 threads
    // bsum (each thread owns one feature)
    float s = 0.f;
    #pragma unroll
    for (int j = 0; j < N_LAYER; j++) s += b[j * N_FEAT + tid];
    g_bsum[tid] = s;

    // 16 dot products, one warp each (warps 0..15)
    int wid = tid >> 5, lane = tid & 31;
    if (wid < N_LAYER * N_LAYER) {
        int j = wid >> 2, i = wid & 3;
        float acc = 0.f;
        #pragma unroll
        for (int k = lane; k < N_FEAT; k += 32)
            acc += b[j * N_FEAT + k] * w[i * N_FEAT + k];
        #pragma unroll
        for (int o = 16; o; o >>= 1)
            acc += __shfl_xor_sync(0xffffffffu, acc, o);
        if (lane == 0) g_h[j][i] = acc;
    }
}

__global__ __launch_bounds__(THREADS) void cross_kernel(
    const float* __restrict__ x, const float* __restrict__ w,
    float* __restrict__ out, int n_rows)
{
    __shared__ float sw[N_LAYER][N_FEAT];
    __shared__ float sbsum[N_FEAT];

    int tid = threadIdx.x;
    for (int i = tid; i < N_LAYER * N_FEAT; i += THREADS)
        (&sw[0][0])[i] = w[i];
    for (int i = tid; i < N_FEAT; i += THREADS)
        sbsum[i] = g_bsum[i];

    float h01 = g_h[0][1];
    float h02 = g_h[0][2] + g_h[1][2];
    float h03 = g_h[0][3] + g_h[1][3] + g_h[2][3];
    __syncthreads();

    int lane = tid & 31;
    int warp = tid >> 5;
    int gwarp = blockIdx.x * WPB + warp;
    int nwarps = gridDim.x * WPB;

    const float4* sw0 = (const float4*)sw[0];
    const float4* sw1 = (const float4*)sw[1];
    const float4* sw2 = (const float4*)sw[2];
    const float4* sw3 = (const float4*)sw[3];
    const float4* sbs = (const float4*)sbsum;

    for (int row = gwarp; row < n_rows; row += nwarps) {
        const float4* xr = (const float4*)(x + (size_t)row * N_FEAT);
        float4 xv[8];
        float g0 = 0.f, g1 = 0.f, g2 = 0.f, g3 = 0.f;
        #pragma unroll
        for (int k = 0; k < 8; k++) {
            int c = lane + 32 * k;       // float4 column index, coalesced
            xv[k] = xr[c];
        }
        #pragma unroll
        for (int k = 0; k < 8; k++) {
            int c = lane + 32 * k;
            float4 w0 = sw0[c], w1 = sw1[c], w2 = sw2[c], w3 = sw3[c];
            g0 += xv[k].x * w0.x + xv[k].y * w0.y + xv[k].z * w0.z + xv[k].w * w0.w;
            g1 += xv[k].x * w1.x + xv[k].y * w1.y + xv[k].z * w1.z + xv[k].w * w1.w;
            g2 += xv[k].x * w2.x + xv[k].y * w2.y + xv[k].z * w2.z + xv[k].w * w2.w;
            g3 += xv[k].x * w3.x + xv[k].y * w3.y + xv[k].z * w3.z + xv[k].w * w3.w;
        }
        #pragma unroll
        for (int o = 16; o; o >>= 1) {
            g0 += __shfl_xor_sync(0xffffffffu, g0, o);
            g1 += __shfl_xor_sync(0xffffffffu, g1, o);
            g2 += __shfl_xor_sync(0xffffffffu, g2, o);
            g3 += __shfl_xor_sync(0xffffffffu, g3, o);
        }
        // scalar recurrence (all lanes redundantly)
        float s1 = 1.f + g0;                  // d0 = g0 (t0 = 0)
        float d1 = s1 * g1 + h01;
        float s2 = s1 + d1;
        float d2 = s2 * g2 + h02;
        float s3 = s2 + d2;
        float d3 = s3 * g3 + h03;
        float s4 = s3 + d3;

        float4* orow = (float4*)(out + (size_t)row * N_FEAT);
        #pragma unroll
        for (int k = 0; k < 8; k++) {
            int c = lane + 32 * k;
            float4 bs = sbs[c];
            float4 o;
            o.x = s4 * xv[k].x + bs.x;
            o.y = s4 * xv[k].y + bs.y;
            o.z = s4 * xv[k].z + bs.z;
            o.w = s4 * xv[k].w + bs.w;
            orow[c] = o;
        }
    }
}

extern "C" void kernel_launch(void* const* d_in, const int* in_sizes, int n_in,
                              void* d_out, int out_size) {
    const float* x = (const float*)d_in[0];
    const float* w = (const float*)d_in[1];
    const float* b = (const float*)d_in[2];
    float* out = (float*)d_out;
    int n_rows = in_sizes[0] / N_FEAT;  // 16384

    precompute_kernel<<<1, 1024>>>(w, b);
    cross_kernel<<<1024, THREADS>>>(x, w, out, n_rows);
}

// round 2
// speedup vs baseline: 1.0179x; 1.0179x over previous
#include <cuda_runtime.h>

#define N_FEAT 1024
#define N_LAYER 4
#define THREADS 256   // one float4 per thread covers the 1024-float row exactly

// Precomputed: hc[0]=h01, hc[1]=h02+h12, hc[2]=h03+h13+h23 where h_ji=<b_j,w_i>
__device__ float g_hc[3];
__device__ float g_bsum[N_FEAT];
__device__ float g_hraw[N_LAYER][N_LAYER];

__global__ __launch_bounds__(1024) void precompute_kernel(
    const float* __restrict__ w, const float* __restrict__ b)
{
    int tid = threadIdx.x;  // 1024 threads
    // bsum: each thread owns one feature
    float s = 0.f;
    #pragma unroll
    for (int j = 0; j < N_LAYER; j++) s += b[j * N_FEAT + tid];
    g_bsum[tid] = s;

    // 16 dot products <b_j, w_i>, one warp each
    int wid = tid >> 5, lane = tid & 31;
    if (wid < N_LAYER * N_LAYER) {
        int j = wid >> 2, i = wid & 3;
        float acc = 0.f;
        #pragma unroll
        for (int k = lane; k < N_FEAT; k += 32)
            acc += b[j * N_FEAT + k] * w[i * N_FEAT + k];
        #pragma unroll
        for (int o = 16; o; o >>= 1)
            acc += __shfl_xor_sync(0xffffffffu, acc, o);
        if (lane == 0) g_hraw[j][i] = acc;
    }
    __syncthreads();
    if (tid == 0) {
        g_hc[0] = g_hraw[0][1];
        g_hc[1] = g_hraw[0][2] + g_hraw[1][2];
        g_hc[2] = g_hraw[0][3] + g_hraw[1][3] + g_hraw[2][3];
    }
}

__global__ __launch_bounds__(THREADS, 6) void cross_kernel(
    const float* __restrict__ x, const float* __restrict__ w,
    float* __restrict__ out)
{
    __shared__ float part[N_LAYER][8];  // [dot][warp]

    const int row  = blockIdx.x;
    const int t    = threadIdx.x;
    const int lane = t & 31;
    const int warp = t >> 5;

    // Load this thread's float4 slice of the row (coalesced, 128B/warp)
    const float4 xv = __ldg((const float4*)(x + (size_t)row * N_FEAT) + t);

    // Weights: same addresses for every block -> L1-resident after first block
    const float4* w4 = (const float4*)w;
    const float4 w0 = __ldg(w4 + 0 * (N_FEAT / 4) + t);
    const float4 w1 = __ldg(w4 + 1 * (N_FEAT / 4) + t);
    const float4 w2 = __ldg(w4 + 2 * (N_FEAT / 4) + t);
    const float4 w3 = __ldg(w4 + 3 * (N_FEAT / 4) + t);

    float p0 = xv.x * w0.x + xv.y * w0.y + xv.z * w0.z + xv.w * w0.w;
    float p1 = xv.x * w1.x + xv.y * w1.y + xv.z * w1.z + xv.w * w1.w;
    float p2 = xv.x * w2.x + xv.y * w2.y + xv.z * w2.z + xv.w * w2.w;
    float p3 = xv.x * w3.x + xv.y * w3.y + xv.z * w3.z + xv.w * w3.w;

    #pragma unroll
    for (int o = 16; o; o >>= 1) {
        p0 += __shfl_xor_sync(0xffffffffu, p0, o);
        p1 += __shfl_xor_sync(0xffffffffu, p1, o);
        p2 += __shfl_xor_sync(0xffffffffu, p2, o);
        p3 += __shfl_xor_sync(0xffffffffu, p3, o);
    }
    if (lane == 0) {
        part[0][warp] = p0;
        part[1][warp] = p1;
        part[2][warp] = p2;
        part[3][warp] = p3;
    }
    __syncthreads();

    // Every thread finishes the reduce redundantly (broadcast LDS, no 2nd sync)
    float g0 = 0.f, g1 = 0.f, g2 = 0.f, g3 = 0.f;
    #pragma unroll
    for (int i = 0; i < 8; i++) {
        g0 += part[0][i];
        g1 += part[1][i];
        g2 += part[2][i];
        g3 += part[3][i];
    }

    const float h01 = g_hc[0], h02 = g_hc[1], h03 = g_hc[2];
    // s_{i+1} = s_i + (s_i*g_i + t-term); x_i = s_i*x0 + sum_{j<i} b_j
    const float s1 = 1.f + g0;
    const float s2 = s1 + s1 * g1 + h01;
    const float s3 = s2 + s2 * g2 + h02;
    const float s4 = s3 + s3 * g3 + h03;

    const float4 bs = __ldg((const float4*)g_bsum + t);
    float4 o;
    o.x = s4 * xv.x + bs.x;
    o.y = s4 * xv.y + bs.y;
    o.z = s4 * xv.z + bs.z;
    o.w = s4 * xv.w + bs.w;
    ((float4*)(out + (size_t)row * N_FEAT))[t] = o;
}

extern "C" void kernel_launch(void* const* d_in, const int* in_sizes, int n_in,
                              void* d_out, int out_size) {
    const float* x = (const float*)d_in[0];
    const float* w = (const float*)d_in[1];
    const float* b = (const float*)d_in[2];
    float* out = (float*)d_out;
    int n_rows = in_sizes[0] / N_FEAT;  // 16384

    precompute_kernel<<<1, 1024>>>(w, b);
    cross_kernel<<<n_rows, THREADS>>>(x, w, out);
}

// round 3
// speedup vs baseline: 1.1014x; 1.0820x over previous
#include <cuda_runtime.h>

#define N_FEAT 1024
#define N_LAYER 4
#define THREADS 256   // one float4 per thread covers a 1024-float row
#define ROWS_PER_BLOCK 8

// Precomputed: hc[0]=h01, hc[1]=h02+h12, hc[2]=h03+h13+h23 where h_ji=<b_j,w_i>
__device__ float g_hc[3];
__device__ float g_bsum[N_FEAT];
__device__ float g_hraw[N_LAYER][N_LAYER];

__global__ __launch_bounds__(1024) void precompute_kernel(
    const float* __restrict__ w, const float* __restrict__ b)
{
    int tid = threadIdx.x;  // 1024 threads
    float s = 0.f;
    #pragma unroll
    for (int j = 0; j < N_LAYER; j++) s += b[j * N_FEAT + tid];
    g_bsum[tid] = s;

    int wid = tid >> 5, lane = tid & 31;
    if (wid < N_LAYER * N_LAYER) {
        int j = wid >> 2, i = wid & 3;
        float acc = 0.f;
        #pragma unroll
        for (int k = lane; k < N_FEAT; k += 32)
            acc += b[j * N_FEAT + k] * w[i * N_FEAT + k];
        #pragma unroll
        for (int o = 16; o; o >>= 1)
            acc += __shfl_xor_sync(0xffffffffu, acc, o);
        if (lane == 0) g_hraw[j][i] = acc;
    }
    __syncthreads();
    if (tid == 0) {
        g_hc[0] = g_hraw[0][1];
        g_hc[1] = g_hraw[0][2] + g_hraw[1][2];
        g_hc[2] = g_hraw[0][3] + g_hraw[1][3] + g_hraw[2][3];
    }
}

__device__ __forceinline__ float dot4(float4 a, float4 b) {
    return a.x * b.x + a.y * b.y + a.z * b.z + a.w * b.w;
}

__global__ __launch_bounds__(THREADS) void cross_kernel(
    const float* __restrict__ x, const float* __restrict__ w,
    float* __restrict__ out)
{
    __shared__ float4 part[2][8];  // [buf][warp] -> (g0,g1,g2,g3) partials

    const int t    = threadIdx.x;
    const int lane = t & 31;
    const int warp = t >> 5;

    // Row-invariant loads, hoisted once per block
    const float4* w4 = (const float4*)w;
    const float4 w0 = __ldg(w4 + 0 * (N_FEAT / 4) + t);
    const float4 w1 = __ldg(w4 + 1 * (N_FEAT / 4) + t);
    const float4 w2 = __ldg(w4 + 2 * (N_FEAT / 4) + t);
    const float4 w3 = __ldg(w4 + 3 * (N_FEAT / 4) + t);
    const float4 bs = __ldg((const float4*)g_bsum + t);
    const float h01 = g_hc[0], h02 = g_hc[1], h03 = g_hc[2];

    const size_t base = (size_t)blockIdx.x * ROWS_PER_BLOCK * (N_FEAT / 4);
    const float4* xp = (const float4*)x + base;
    float4*       op = (float4*)out + base;

    float4 xv = __ldg(xp + t);  // prefetch row 0

    #pragma unroll
    for (int r = 0; r < ROWS_PER_BLOCK; r++) {
        float4 xn;
        if (r + 1 < ROWS_PER_BLOCK)
            xn = __ldg(xp + (size_t)(r + 1) * (N_FEAT / 4) + t);

        float p0 = dot4(xv, w0);
        float p1 = dot4(xv, w1);
        float p2 = dot4(xv, w2);
        float p3 = dot4(xv, w3);

        // Stages 16, 8: all four partials. Afterwards each lane holds the
        // sum over its (lane mod 8) class for every dot.
        #pragma unroll
        for (int o = 16; o >= 8; o >>= 1) {
            p0 += __shfl_xor_sync(0xffffffffu, p0, o);
            p1 += __shfl_xor_sync(0xffffffffu, p1, o);
            p2 += __shfl_xor_sync(0xffffffffu, p2, o);
            p3 += __shfl_xor_sync(0xffffffffu, p3, o);
        }
        // Lane-group g (8 lanes) takes dot g; 3 more stages within the group.
        const int grp = lane >> 3;
        float q = (grp == 0) ? p0 : (grp == 1) ? p1 : (grp == 2) ? p2 : p3;
        q += __shfl_xor_sync(0xffffffffu, q, 4);
        q += __shfl_xor_sync(0xffffffffu, q, 2);
        q += __shfl_xor_sync(0xffffffffu, q, 1);

        const int buf = r & 1;
        if ((lane & 7) == 0)
            ((float*)&part[buf][warp])[grp] = q;
        __syncthreads();

        // Cross-warp finish, redundantly per thread (broadcast LDS.128)
        float4 g = part[buf][0];
        #pragma unroll
        for (int i = 1; i < 8; i++) {
            float4 v = part[buf][i];
            g.x += v.x; g.y += v.y; g.z += v.z; g.w += v.w;
        }

        const float s1 = 1.f + g.x;
        const float s2 = s1 + s1 * g.y + h01;
        const float s3 = s2 + s2 * g.z + h02;
        const float s4 = s3 + s3 * g.w + h03;

        float4 o;
        o.x = s4 * xv.x + bs.x;
        o.y = s4 * xv.y + bs.y;
        o.z = s4 * xv.z + bs.z;
        o.w = s4 * xv.w + bs.w;
        op[(size_t)r * (N_FEAT / 4) + t] = o;

        xv = xn;
    }
}

extern "C" void kernel_launch(void* const* d_in, const int* in_sizes, int n_in,
                              void* d_out, int out_size) {
    const float* x = (const float*)d_in[0];
    const float* w = (const float*)d_in[1];
    const float* b = (const float*)d_in[2];
    float* out = (float*)d_out;
    int n_rows = in_sizes[0] / N_FEAT;  // 16384

    precompute_kernel<<<1, 1024>>>(w, b);
    cross_kernel<<<n_rows / ROWS_PER_BLOCK, THREADS>>>(x, w, out);
}

// round 4
// speedup vs baseline: 1.1100x; 1.0078x over previous
#include <cuda_runtime.h>

#define N_FEAT 1024
#define N_LAYER 4
#define THREADS 256   // one float4 per thread covers a 1024-float row
#define ROWS_PER_BLOCK 8

// Precomputed: hc[0]=h01, hc[1]=h02+h12, hc[2]=h03+h13+h23 where h_ji=<b_j,w_i>
__device__ float g_hc[3];
__device__ float g_bsum[N_FEAT];
__device__ float g_hraw[N_LAYER][N_LAYER];

__global__ __launch_bounds__(1024) void precompute_kernel(
    const float* __restrict__ w, const float* __restrict__ b)
{
    int tid = threadIdx.x;  // 1024 threads
    float s = 0.f;
    #pragma unroll
    for (int j = 0; j < N_LAYER; j++) s += b[j * N_FEAT + tid];
    g_bsum[tid] = s;

    int wid = tid >> 5, lane = tid & 31;
    if (wid < N_LAYER * N_LAYER) {
        int j = wid >> 2, i = wid & 3;
        float acc = 0.f;
        #pragma unroll
        for (int k = lane; k < N_FEAT; k += 32)
            acc += b[j * N_FEAT + k] * w[i * N_FEAT + k];
        #pragma unroll
        for (int o = 16; o; o >>= 1)
            acc += __shfl_xor_sync(0xffffffffu, acc, o);
        if (lane == 0) g_hraw[j][i] = acc;
    }
    __syncthreads();
    if (tid == 0) {
        g_hc[0] = g_hraw[0][1];
        g_hc[1] = g_hraw[0][2] + g_hraw[1][2];
        g_hc[2] = g_hraw[0][3] + g_hraw[1][3] + g_hraw[2][3];
    }
}

__device__ __forceinline__ float dot4(float4 a, float4 b) {
    return a.x * b.x + a.y * b.y + a.z * b.z + a.w * b.w;
}

__global__ __launch_bounds__(THREADS) void cross_kernel(
    const float* __restrict__ x, const float* __restrict__ w,
    float* __restrict__ out)
{
    __shared__ float4 part[2][8];  // [buf][warp] -> (g0,g1,g2,g3) partials

    const int t    = threadIdx.x;
    const int lane = t & 31;
    const int warp = t >> 5;

    // Row-invariant loads, hoisted once per block
    const float4* w4 = (const float4*)w;
    const float4 w0 = __ldg(w4 + 0 * (N_FEAT / 4) + t);
    const float4 w1 = __ldg(w4 + 1 * (N_FEAT / 4) + t);
    const float4 w2 = __ldg(w4 + 2 * (N_FEAT / 4) + t);
    const float4 w3 = __ldg(w4 + 3 * (N_FEAT / 4) + t);
    const float4 bs = __ldg((const float4*)g_bsum + t);
    const float h01 = g_hc[0], h02 = g_hc[1], h03 = g_hc[2];

    const size_t base = (size_t)blockIdx.x * ROWS_PER_BLOCK * (N_FEAT / 4);
    const float4* xp = (const float4*)x + base;
    float4*       op = (float4*)out + base;

    float4 xv = __ldg(xp + t);  // prefetch row 0

    #pragma unroll
    for (int r = 0; r < ROWS_PER_BLOCK; r++) {
        float4 xn;
        if (r + 1 < ROWS_PER_BLOCK)
            xn = __ldg(xp + (size_t)(r + 1) * (N_FEAT / 4) + t);

        float p0 = dot4(xv, w0);
        float p1 = dot4(xv, w1);
        float p2 = dot4(xv, w2);
        float p3 = dot4(xv, w3);

        // Stages 16, 8: all four partials. Afterwards each lane holds the
        // sum over its (lane mod 8) class for every dot.
        #pragma unroll
        for (int o = 16; o >= 8; o >>= 1) {
            p0 += __shfl_xor_sync(0xffffffffu, p0, o);
            p1 += __shfl_xor_sync(0xffffffffu, p1, o);
            p2 += __shfl_xor_sync(0xffffffffu, p2, o);
            p3 += __shfl_xor_sync(0xffffffffu, p3, o);
        }
        // Lane-group g (8 lanes) takes dot g; 3 more stages within the group.
        const int grp = lane >> 3;
        float q = (grp == 0) ? p0 : (grp == 1) ? p1 : (grp == 2) ? p2 : p3;
        q += __shfl_xor_sync(0xffffffffu, q, 4);
        q += __shfl_xor_sync(0xffffffffu, q, 2);
        q += __shfl_xor_sync(0xffffffffu, q, 1);

        const int buf = r & 1;
        if ((lane & 7) == 0)
            ((float*)&part[buf][warp])[grp] = q;
        __syncthreads();

        // Cross-warp finish, redundantly per thread (broadcast LDS.128)
        float4 g = part[buf][0];
        #pragma unroll
        for (int i = 1; i < 8; i++) {
            float4 v = part[buf][i];
            g.x += v.x; g.y += v.y; g.z += v.z; g.w += v.w;
        }

        const float s1 = 1.f + g.x;
        const float s2 = s1 + s1 * g.y + h01;
        const float s3 = s2 + s2 * g.z + h02;
        const float s4 = s3 + s3 * g.w + h03;

        float4 o;
        o.x = s4 * xv.x + bs.x;
        o.y = s4 * xv.y + bs.y;
        o.z = s4 * xv.z + bs.z;
        o.w = s4 * xv.w + bs.w;
        op[(size_t)r * (N_FEAT / 4) + t] = o;

        xv = xn;
    }
}

extern "C" void kernel_launch(void* const* d_in, const int* in_sizes, int n_in,
                              void* d_out, int out_size) {
    const float* x = (const float*)d_in[0];
    const float* w = (const float*)d_in[1];
    const float* b = (const float*)d_in[2];
    float* out = (float*)d_out;
    int n_rows = in_sizes[0] / N_FEAT;  // 16384

    precompute_kernel<<<1, 1024>>>(w, b);
    cross_kernel<<<n_rows / ROWS_PER_BLOCK, THREADS>>>(x, w, out);
}

// round 5
// speedup vs baseline: 1.2889x; 1.1612x over previous
#include <cuda_runtime.h>

#define N_FEAT 1024
#define N_LAYER 4
#define THREADS 256        // one float4 per thread covers a 1024-float row
#define R 4                // rows per block, all in flight simultaneously

// Precomputed: hc[0]=h01, hc[1]=h02+h12, hc[2]=h03+h13+h23 where h_ji=<b_j,w_i>
__device__ float g_hc[3];
__device__ float g_bsum[N_FEAT];
__device__ float g_hraw[N_LAYER][N_LAYER];

__global__ __launch_bounds__(1024) void precompute_kernel(
    const float* __restrict__ w, const float* __restrict__ b)
{
    int tid = threadIdx.x;  // 1024 threads
    float s = 0.f;
    #pragma unroll
    for (int j = 0; j < N_LAYER; j++) s += b[j * N_FEAT + tid];
    g_bsum[tid] = s;

    int wid = tid >> 5, lane = tid & 31;
    if (wid < N_LAYER * N_LAYER) {
        int j = wid >> 2, i = wid & 3;
        float acc = 0.f;
        #pragma unroll
        for (int k = lane; k < N_FEAT; k += 32)
            acc += b[j * N_FEAT + k] * w[i * N_FEAT + k];
        #pragma unroll
        for (int o = 16; o; o >>= 1)
            acc += __shfl_xor_sync(0xffffffffu, acc, o);
        if (lane == 0) g_hraw[j][i] = acc;
    }
    __syncthreads();
    if (tid == 0) {
        g_hc[0] = g_hraw[0][1];
        g_hc[1] = g_hraw[0][2] + g_hraw[1][2];
        g_hc[2] = g_hraw[0][3] + g_hraw[1][3] + g_hraw[2][3];
    }
}

__device__ __forceinline__ float dot4(float4 a, float4 b) {
    return a.x * b.x + a.y * b.y + a.z * b.z + a.w * b.w;
}

__global__ __launch_bounds__(THREADS) void cross_kernel(
    const float* __restrict__ x, const float* __restrict__ w,
    float* __restrict__ out)
{
    __shared__ float4 part[R][8];  // [row][warp] -> (g0,g1,g2,g3) partials

    const int t    = threadIdx.x;
    const int lane = t & 31;
    const int warp = t >> 5;
    const int grp  = lane >> 3;

    // Row-invariant loads, once per block
    const float4* w4 = (const float4*)w;
    const float4 w0 = __ldg(w4 + 0 * (N_FEAT / 4) + t);
    const float4 w1 = __ldg(w4 + 1 * (N_FEAT / 4) + t);
    const float4 w2 = __ldg(w4 + 2 * (N_FEAT / 4) + t);
    const float4 w3 = __ldg(w4 + 3 * (N_FEAT / 4) + t);
    const float4 bs = __ldg((const float4*)g_bsum + t);
    const float h01 = g_hc[0], h02 = g_hc[1], h03 = g_hc[2];

    const size_t base = (size_t)blockIdx.x * R * (N_FEAT / 4);
    const float4* xp = (const float4*)x + base;
    float4*       op = (float4*)out + base;

    // ── Phase A: batch all R row loads, then R independent dot+reduce chains
    float4 xv[R];
    #pragma unroll
    for (int r = 0; r < R; r++)
        xv[r] = __ldg(xp + (size_t)r * (N_FEAT / 4) + t);

    #pragma unroll
    for (int r = 0; r < R; r++) {
        float p0 = dot4(xv[r], w0);
        float p1 = dot4(xv[r], w1);
        float p2 = dot4(xv[r], w2);
        float p3 = dot4(xv[r], w3);

        // Stages 16, 8 on all four dots; afterwards each lane holds the sum
        // over its (lane & 7) class for every dot.
        #pragma unroll
        for (int o = 16; o >= 8; o >>= 1) {
            p0 += __shfl_xor_sync(0xffffffffu, p0, o);
            p1 += __shfl_xor_sync(0xffffffffu, p1, o);
            p2 += __shfl_xor_sync(0xffffffffu, p2, o);
            p3 += __shfl_xor_sync(0xffffffffu, p3, o);
        }
        // Lane-group g (8 lanes) finishes dot g: 3 more stages
        float q = (grp == 0) ? p0 : (grp == 1) ? p1 : (grp == 2) ? p2 : p3;
        q += __shfl_xor_sync(0xffffffffu, q, 4);
        q += __shfl_xor_sync(0xffffffffu, q, 2);
        q += __shfl_xor_sync(0xffffffffu, q, 1);

        if ((lane & 7) == 0)
            ((float*)&part[r][warp])[grp] = q;
    }

    __syncthreads();  // the only barrier in the kernel

    // ── Phase B: R independent reduce -> s4 -> store chains
    #pragma unroll
    for (int r = 0; r < R; r++) {
        float4 g = part[r][0];
        #pragma unroll
        for (int i = 1; i < 8; i++) {
            float4 v = part[r][i];
            g.x += v.x; g.y += v.y; g.z += v.z; g.w += v.w;
        }
        const float s1 = 1.f + g.x;
        const float s2 = s1 + s1 * g.y + h01;
        const float s3 = s2 + s2 * g.z + h02;
        const float s4 = s3 + s3 * g.w + h03;

        float4 o;
        o.x = s4 * xv[r].x + bs.x;
        o.y = s4 * xv[r].y + bs.y;
        o.z = s4 * xv[r].z + bs.z;
        o.w = s4 * xv[r].w + bs.w;
        op[(size_t)r * (N_FEAT / 4) + t] = o;
    }
}

extern "C" void kernel_launch(void* const* d_in, const int* in_sizes, int n_in,
                              void* d_out, int out_size) {
    const float* x = (const float*)d_in[0];
    const float* w = (const float*)d_in[1];
    const float* b = (const float*)d_in[2];
    float* out = (float*)d_out;
    int n_rows = in_sizes[0] / N_FEAT;  // 16384

    precompute_kernel<<<1, 1024>>>(w, b);
    cross_kernel<<<n_rows / R, THREADS>>>(x, w, out);
}

// round 6
// speedup vs baseline: 1.4580x; 1.1311x over previous
#include <cuda_runtime.h>

#define N_FEAT 1024
#define N_LAYER 4
#define THREADS 256        // one float4 per thread covers a 1024-float row
#define R 4                // rows per block

// Precomputed: hc[0]=h01, hc[1]=h02+h12, hc[2]=h03+h13+h23 where h_ji=<b_j,w_i>
__device__ float g_hc[3];
__device__ float g_bsum[N_FEAT];
__device__ float g_hraw[N_LAYER][N_LAYER];

__global__ __launch_bounds__(1024) void precompute_kernel(
    const float* __restrict__ w, const float* __restrict__ b)
{
    int tid = threadIdx.x;  // 1024 threads
    float s = 0.f;
    #pragma unroll
    for (int j = 0; j < N_LAYER; j++) s += b[j * N_FEAT + tid];
    g_bsum[tid] = s;

    int wid = tid >> 5, lane = tid & 31;
    if (wid < N_LAYER * N_LAYER) {
        int j = wid >> 2, i = wid & 3;
        float acc = 0.f;
        #pragma unroll
        for (int k = lane; k < N_FEAT; k += 32)
            acc += b[j * N_FEAT + k] * w[i * N_FEAT + k];
        #pragma unroll
        for (int o = 16; o; o >>= 1)
            acc += __shfl_xor_sync(0xffffffffu, acc, o);
        if (lane == 0) g_hraw[j][i] = acc;
    }
    __syncthreads();
    if (tid == 0) {
        g_hc[0] = g_hraw[0][1];
        g_hc[1] = g_hraw[0][2] + g_hraw[1][2];
        g_hc[2] = g_hraw[0][3] + g_hraw[1][3] + g_hraw[2][3];
    }
}

__device__ __forceinline__ float dot4(float4 a, float4 b) {
    return a.x * b.x + a.y * b.y + a.z * b.z + a.w * b.w;
}

__global__ __launch_bounds__(THREADS, 6) void cross_kernel(
    const float* __restrict__ x, const float* __restrict__ w,
    float* __restrict__ out)
{
    __shared__ float4 part[R][THREADS];  // per-thread dot partials (16 KB)
    __shared__ float  s4s[R];

    const int t    = threadIdx.x;
    const int lane = t & 31;
    const int warp = t >> 5;

    const size_t base = (size_t)blockIdx.x * R * (N_FEAT / 4);
    const float4* xp = (const float4*)x + base;
    float4*       op = (float4*)out + base;

    // ── Phase A: dot partials, no shuffles — one STS.128 per row
    {
        const float4* w4 = (const float4*)w;
        const float4 w0 = __ldg(w4 + 0 * (N_FEAT / 4) + t);
        const float4 w1 = __ldg(w4 + 1 * (N_FEAT / 4) + t);
        const float4 w2 = __ldg(w4 + 2 * (N_FEAT / 4) + t);
        const float4 w3 = __ldg(w4 + 3 * (N_FEAT / 4) + t);
        #pragma unroll
        for (int r = 0; r < R; r++) {
            const float4 xv = __ldg(xp + (size_t)r * (N_FEAT / 4) + t);
            float4 p;
            p.x = dot4(xv, w0);
            p.y = dot4(xv, w1);
            p.z = dot4(xv, w2);
            p.w = dot4(xv, w3);
            part[r][t] = p;
        }
    }
    __syncthreads();

    // ── Phase B: warp r reduces row r (8 LDS.128 + 20 SHFL)
    if (warp < R) {
        float4 acc = part[warp][lane];
        #pragma unroll
        for (int j = 1; j < 8; j++) {
            float4 v = part[warp][lane + 32 * j];
            acc.x += v.x; acc.y += v.y; acc.z += v.z; acc.w += v.w;
        }
        #pragma unroll
        for (int o = 16; o; o >>= 1) {
            acc.x += __shfl_xor_sync(0xffffffffu, acc.x, o);
            acc.y += __shfl_xor_sync(0xffffffffu, acc.y, o);
            acc.z += __shfl_xor_sync(0xffffffffu, acc.z, o);
            acc.w += __shfl_xor_sync(0xffffffffu, acc.w, o);
        }
        if (lane == 0) {
            const float s1 = 1.f + acc.x;
            const float s2 = s1 + s1 * acc.y + g_hc[0];
            const float s3 = s2 + s2 * acc.z + g_hc[1];
            const float s4 = s3 + s3 * acc.w + g_hc[2];
            s4s[warp] = s4;
        }
    }
    __syncthreads();

    // ── Phase C: re-read x (L1-hot), scale, add bsum, store
    {
        const float4 bs = __ldg((const float4*)g_bsum + t);
        float sc[R];
        #pragma unroll
        for (int r = 0; r < R; r++) sc[r] = s4s[r];

        #pragma unroll
        for (int r = 0; r < R; r++) {
            const float4 xv = __ldg(xp + (size_t)r * (N_FEAT / 4) + t);
            float4 o;
            o.x = sc[r] * xv.x + bs.x;
            o.y = sc[r] * xv.y + bs.y;
            o.z = sc[r] * xv.z + bs.z;
            o.w = sc[r] * xv.w + bs.w;
            op[(size_t)r * (N_FEAT / 4) + t] = o;
        }
    }
}

extern "C" void kernel_launch(void* const* d_in, const int* in_sizes, int n_in,
                              void* d_out, int out_size) {
    const float* x = (const float*)d_in[0];
    const float* w = (const float*)d_in[1];
    const float* b = (const float*)d_in[2];
    float* out = (float*)d_out;
    int n_rows = in_sizes[0] / N_FEAT;  // 16384

    precompute_kernel<<<1, 1024>>>(w, b);
    cross_kernel<<<n_rows / R, THREADS>>>(x, w, out);
}

// round 7
// speedup vs baseline: 1.4610x; 1.0021x over previous
#include <cuda_runtime.h>

#define N_FEAT 1024
#define N_LAYER 4
#define THREADS 256        // one float4 per thread covers a 1024-float row
#define R 4                // rows per block

// Precomputed: hc[0]=h01, hc[1]=h02+h12, hc[2]=h03+h13+h23 where h_ji=<b_j,w_i>
__device__ float g_hc[3];
__device__ float g_bsum[N_FEAT];
__device__ float g_hraw[N_LAYER][N_LAYER];

__global__ __launch_bounds__(1024) void precompute_kernel(
    const float* __restrict__ w, const float* __restrict__ b)
{
    int tid = threadIdx.x;  // 1024 threads
    float s = 0.f;
    #pragma unroll
    for (int j = 0; j < N_LAYER; j++) s += b[j * N_FEAT + tid];
    g_bsum[tid] = s;

    int wid = tid >> 5, lane = tid & 31;
    if (wid < N_LAYER * N_LAYER) {
        int j = wid >> 2, i = wid & 3;
        float acc = 0.f;
        #pragma unroll
        for (int k = lane; k < N_FEAT; k += 32)
            acc += b[j * N_FEAT + k] * w[i * N_FEAT + k];
        #pragma unroll
        for (int o = 16; o; o >>= 1)
            acc += __shfl_xor_sync(0xffffffffu, acc, o);
        if (lane == 0) g_hraw[j][i] = acc;
    }
    __syncthreads();
    if (tid == 0) {
        g_hc[0] = g_hraw[0][1];
        g_hc[1] = g_hraw[0][2] + g_hraw[1][2];
        g_hc[2] = g_hraw[0][3] + g_hraw[1][3] + g_hraw[2][3];
    }
}

__device__ __forceinline__ float dot4(float4 a, float4 b) {
    return a.x * b.x + a.y * b.y + a.z * b.z + a.w * b.w;
}

__global__ __launch_bounds__(THREADS, 6) void cross_kernel(
    const float* __restrict__ x, const float* __restrict__ w,
    float* __restrict__ out)
{
    __shared__ float4 part[R][THREADS];  // per-thread dot partials (16 KB)
    __shared__ float  s4s[R];

    const int t    = threadIdx.x;
    const int lane = t & 31;
    const int warp = t >> 5;

    const size_t base = (size_t)blockIdx.x * R * (N_FEAT / 4);
    const float4* xp = (const float4*)x + base;
    float4*       op = (float4*)out + base;

    // ── Phase A: dot partials, no shuffles — one STS.128 per row
    {
        const float4* w4 = (const float4*)w;
        const float4 w0 = __ldg(w4 + 0 * (N_FEAT / 4) + t);
        const float4 w1 = __ldg(w4 + 1 * (N_FEAT / 4) + t);
        const float4 w2 = __ldg(w4 + 2 * (N_FEAT / 4) + t);
        const float4 w3 = __ldg(w4 + 3 * (N_FEAT / 4) + t);
        #pragma unroll
        for (int r = 0; r < R; r++) {
            const float4 xv = __ldg(xp + (size_t)r * (N_FEAT / 4) + t);
            float4 p;
            p.x = dot4(xv, w0);
            p.y = dot4(xv, w1);
            p.z = dot4(xv, w2);
            p.w = dot4(xv, w3);
            part[r][t] = p;
        }
    }
    __syncthreads();

    // ── Phase B: warp r reduces row r (8 LDS.128 + 20 SHFL)
    if (warp < R) {
        float4 acc = part[warp][lane];
        #pragma unroll
        for (int j = 1; j < 8; j++) {
            float4 v = part[warp][lane + 32 * j];
            acc.x += v.x; acc.y += v.y; acc.z += v.z; acc.w += v.w;
        }
        #pragma unroll
        for (int o = 16; o; o >>= 1) {
            acc.x += __shfl_xor_sync(0xffffffffu, acc.x, o);
            acc.y += __shfl_xor_sync(0xffffffffu, acc.y, o);
            acc.z += __shfl_xor_sync(0xffffffffu, acc.z, o);
            acc.w += __shfl_xor_sync(0xffffffffu, acc.w, o);
        }
        if (lane == 0) {
            const float s1 = 1.f + acc.x;
            const float s2 = s1 + s1 * acc.y + g_hc[0];
            const float s3 = s2 + s2 * acc.z + g_hc[1];
            const float s4 = s3 + s3 * acc.w + g_hc[2];
            s4s[warp] = s4;
        }
    }
    __syncthreads();

    // ── Phase C: re-read x (L1-hot), scale, add bsum, store
    {
        const float4 bs = __ldg((const float4*)g_bsum + t);
        float sc[R];
        #pragma unroll
        for (int r = 0; r < R; r++) sc[r] = s4s[r];

        #pragma unroll
        for (int r = 0; r < R; r++) {
            const float4 xv = __ldg(xp + (size_t)r * (N_FEAT / 4) + t);
            float4 o;
            o.x = sc[r] * xv.x + bs.x;
            o.y = sc[r] * xv.y + bs.y;
            o.z = sc[r] * xv.z + bs.z;
            o.w = sc[r] * xv.w + bs.w;
            op[(size_t)r * (N_FEAT / 4) + t] = o;
        }
    }
}

extern "C" void kernel_launch(void* const* d_in, const int* in_sizes, int n_in,
                              void* d_out, int out_size) {
    const float* x = (const float*)d_in[0];
    const float* w = (const float*)d_in[1];
    const float* b = (const float*)d_in[2];
    float* out = (float*)d_out;
    int n_rows = in_sizes[0] / N_FEAT;  // 16384

    precompute_kernel<<<1, 1024>>>(w, b);
    cross_kernel<<<n_rows / R, THREADS>>>(x, w, out);
}